// round 2
// baseline (speedup 1.0000x reference)
#include <cuda_runtime.h>

#define BB 64
#define CC 64
#define TT 4096

// Accurate fast tanh: EX2 + RCP (2 MUFU), rel err ~1e-6.
__device__ __forceinline__ float tanh_fast(float x) {
    float xc = fminf(fmaxf(x, -15.0f), 15.0f);
    float e  = __expf(2.0f * xc);
    return __fdividef(e - 1.0f, e + 1.0f);
}

// ---------------------------------------------------------------------------
// Kernel 1: sequential recurrence, one CTA per batch row.
// 128 threads: thread = (channel c = tid>>1, K-half h = tid&1).
// Each thread holds W_rec[c, 32h : 32h+32] in registers.
// tanh(x) broadcast via double-buffered shared array, ONE __syncthreads/step.
// Lane pair (2c, 2c+1) reduces its two K-halves with shfl_xor; both lanes
// redundantly (bit-identically) update x -> deterministic, no 2nd barrier.
// ---------------------------------------------------------------------------
struct RecState { float x; float th; };

__device__ __forceinline__ void rec_step(
    RecState& s, float ut, int buf, int c, int h, float dt,
    const float* __restrict__ w, float (*th_sh)[CC])
{
    if (h == 0) th_sh[buf][c] = s.th;
    __syncthreads();
    const float4* thv = (const float4*)(&th_sh[buf][h * 32]);
    float a0 = 0.f, a1 = 0.f, a2 = 0.f, a3 = 0.f;
#pragma unroll
    for (int j = 0; j < 8; j++) {
        float4 v = thv[j];
        a0 = fmaf(w[4 * j + 0], v.x, a0);
        a1 = fmaf(w[4 * j + 1], v.y, a1);
        a2 = fmaf(w[4 * j + 2], v.z, a2);
        a3 = fmaf(w[4 * j + 3], v.w, a3);
    }
    float sum = (a0 + a1) + (a2 + a3);
    sum += __shfl_xor_sync(0xffffffffu, sum, 1);   // full K=64 on both lanes
    s.x  = fmaf(dt, (sum + ut) - s.x, s.x);        // x += dt*(-x + rec + u)
    s.th = tanh_fast(s.x);
}

__global__ __launch_bounds__(128, 1)
void rec_kernel(const float* __restrict__ u, const float* __restrict__ Wrec,
                const float* __restrict__ dtp, float* __restrict__ xmem) {
    const int b   = blockIdx.x;
    const int tid = threadIdx.x;
    const int c   = tid >> 1;
    const int h   = tid & 1;

    __shared__ float th_sh[2][CC];

    float w[32];
#pragma unroll
    for (int j = 0; j < 32; j++) w[j] = Wrec[c * CC + h * 32 + j];

    const float dt = *dtp;
    const float4* ub4 = (const float4*)(u    + (b * CC + c) * TT);
    float4*       xb4 = (float4*)      (xmem + (b * CC + c) * TT);

    RecState s; s.x = 0.0f; s.th = 0.0f;          // x0 = 0, tanh(0) = 0
    float4 ucur  = ub4[0];
    float4 unext = ub4[1];

    for (int t0 = 0; t0 < TT; t0 += 4) {
        float4 xout;
        rec_step(s, ucur.x, 0, c, h, dt, w, th_sh); xout.x = s.x;
        rec_step(s, ucur.y, 1, c, h, dt, w, th_sh); xout.y = s.x;
        rec_step(s, ucur.z, 0, c, h, dt, w, th_sh); xout.z = s.x;
        rec_step(s, ucur.w, 1, c, h, dt, w, th_sh); xout.w = s.x;
        if (h == 0) xb4[t0 >> 2] = xout;           // membrane trace
        ucur = unext;
        if (t0 + 8 < TT) unext = ub4[(t0 >> 2) + 2];
    }
}

// ---------------------------------------------------------------------------
// Kernel 2: time-parallel readout  y[b,c,t] = sum_k Wff[c,k]*x[b,k,t] + bff[c]
// Block = (t-tile of 128, batch b). x tile [64][128] staged in shared; every
// MAC-loop LDS is a full-warp broadcast (lanes share (k, t-range), differ in c).
// W_ff staged transposed -> conflict-free per-k weight loads.
// ---------------------------------------------------------------------------
__global__ __launch_bounds__(256)
void ff_kernel(const float* __restrict__ xmem, const float* __restrict__ Wff,
               const float* __restrict__ bff, float* __restrict__ y) {
    const int tt  = blockIdx.x;          // 0..31  -> t0 = tt*128
    const int b   = blockIdx.y;          // 0..63
    const int tid = threadIdx.x;         // 0..255
    const int c   = tid & 63;
    const int q   = tid >> 6;            // t-quarter 0..3
    const int t0  = tt * 128;

    __shared__ float xs[CC * 128];       // 32 KB, [k][t] row-major
    __shared__ float wsh[CC * CC];       // 16 KB, transposed: wsh[k*64 + c]

    // stage x tile (coalesced along t)
    const float4* xg4 = (const float4*)xmem;
    float4* xs4 = (float4*)xs;
#pragma unroll
    for (int i = 0; i < 8; i++) {
        int f   = tid + 256 * i;         // 0..2047 float4s
        int row = f >> 5;
        int col = f & 31;
        xs4[f] = xg4[(b * CC + row) * (TT / 4) + (t0 >> 2) + col];
    }
    // stage W_ff transposed (one-time STS conflicts, negligible)
#pragma unroll
    for (int i = 0; i < 16; i++) {
        int f = tid + 256 * i;           // f = c_src*64 + k_src
        int csrc = f >> 6, ksrc = f & 63;
        wsh[ksrc * 64 + csrc] = Wff[f];
    }

    float bias = bff[c];
    float4 acc[8];
#pragma unroll
    for (int j = 0; j < 8; j++) acc[j] = make_float4(bias, bias, bias, bias);

    __syncthreads();

    const float4* xrowq = (const float4*)(xs) + q * 8;  // this quarter's 32 t's
#pragma unroll 8
    for (int k = 0; k < CC; k++) {
        float wv = wsh[k * 64 + c];                     // conflict-free
        const float4* xr = xrowq + k * 32;
#pragma unroll
        for (int j = 0; j < 8; j++) {
            float4 v = xr[j];                           // warp-broadcast LDS
            acc[j].x = fmaf(wv, v.x, acc[j].x);
            acc[j].y = fmaf(wv, v.y, acc[j].y);
            acc[j].z = fmaf(wv, v.z, acc[j].z);
            acc[j].w = fmaf(wv, v.w, acc[j].w);
        }
    }

    float4* y4 = (float4*)(y + (b * CC + c) * TT + t0 + q * 32);
#pragma unroll
    for (int j = 0; j < 8; j++) y4[j] = acc[j];
}

// ---------------------------------------------------------------------------
extern "C" void kernel_launch(void* const* d_in, const int* in_sizes, int n_in,
                              void* d_out, int out_size) {
    const float* u    = (const float*)d_in[0];   // [B,C,T]
    const float* Wrec = (const float*)d_in[1];   // [C,C]
    const float* Wff  = (const float*)d_in[2];   // [C,C]
    const float* bff  = (const float*)d_in[3];   // [C]
    const float* dtp  = (const float*)d_in[4];   // scalar

    float* out  = (float*)d_out;
    float* yout = out;                            // outputs [B,C,T]
    float* xmem = out + (size_t)BB * CC * TT;     // membrane_potentials [B,C,T]

    rec_kernel<<<BB, 128>>>(u, Wrec, dtp, xmem);

    dim3 g2(TT / 128, BB);
    ff_kernel<<<g2, 256>>>(xmem, Wff, bff, yout);
}

// round 4
// speedup vs baseline: 1.0742x; 1.0742x over previous
#include <cuda_runtime.h>

#define BB 64
#define CC 64
#define TT 4096

// ---- packed f32x2 helpers (Blackwell FFMA2 path, PTX-only) -----------------
__device__ __forceinline__ unsigned long long pk2(float lo, float hi) {
    unsigned long long r;
    asm("mov.b64 %0, {%1, %2};" : "=l"(r) : "f"(lo), "f"(hi));
    return r;
}
__device__ __forceinline__ void upk2(float& lo, float& hi, unsigned long long v) {
    asm("mov.b64 {%0, %1}, %2;" : "=f"(lo), "=f"(hi) : "l"(v));
}
__device__ __forceinline__ unsigned long long fma2(unsigned long long a,
                                                   unsigned long long b,
                                                   unsigned long long c) {
    unsigned long long d;
    asm("fma.rn.f32x2 %0, %1, %2, %3;" : "=l"(d) : "l"(a), "l"(b), "l"(c));
    return d;
}
__device__ __forceinline__ unsigned long long add2(unsigned long long a,
                                                   unsigned long long b) {
    unsigned long long d;
    asm("add.rn.f32x2 %0, %1, %2;" : "=l"(d) : "l"(a), "l"(b));
    return d;
}

// ---- MUFU primitives via PTX (independent of -use_fast_math) ---------------
__device__ __forceinline__ float ex2_approx(float x) {
    float r;
    asm("ex2.approx.f32 %0, %1;" : "=f"(r) : "f"(x));
    return r;
}
__device__ __forceinline__ float rcp_approx(float x) {
    float r;
    asm("rcp.approx.f32 %0, %1;" : "=f"(r) : "f"(x));
    return r;
}

// tanh(x) = 1 - 2/(1 + e^{2x}); clampless (overflow -> correct +-1 limit).
// chain: FMUL(4)+EX2(16)+FADD(4)+RCP(16)+FFMA(4) ~= 44 cyc, rel err ~1e-6.
__device__ __forceinline__ float tanh_fast(float x) {
    float e = ex2_approx(x * 2.885390082f);       // e^{2x} = 2^{x*2*log2(e)}
    float r = rcp_approx(e + 1.0f);
    return fmaf(-2.0f, r, 1.0f);
}

// ---------------------------------------------------------------------------
// Kernel 1: sequential recurrence, one CTA per batch row.
// 128 threads: thread = (channel c = tid>>1, K-half h = tid&1).
// Each thread holds W_rec[c, 32h:32h+32] as 16 packed f32x2 registers.
// tanh(x) broadcast via double-buffered shared array, ONE __syncthreads/step.
// Lane pair (2c,2c+1) reduces its halves with shfl_xor; both lanes update x
// bit-identically (no second barrier).
// ---------------------------------------------------------------------------
__device__ __forceinline__ void rec_step(
    float& x, float& th, float ut, int buf, int c, int h, float dt,
    const unsigned long long* __restrict__ w2, float (*th_sh)[CC])
{
    if (h == 0) th_sh[buf][c] = th;
    __syncthreads();
    const ulonglong2* thv = (const ulonglong2*)(&th_sh[buf][h * 32]);
    unsigned long long a0 = 0ull, a1 = 0ull, a2 = 0ull, a3 = 0ull;
#pragma unroll
    for (int j = 0; j < 8; j += 2) {
        ulonglong2 v0 = thv[j];
        ulonglong2 v1 = thv[j + 1];
        a0 = fma2(w2[2 * j + 0], v0.x, a0);
        a1 = fma2(w2[2 * j + 1], v0.y, a1);
        a2 = fma2(w2[2 * j + 2], v1.x, a2);
        a3 = fma2(w2[2 * j + 3], v1.y, a3);
    }
    unsigned long long sp = add2(add2(a0, a1), add2(a2, a3));
    float lo, hi; upk2(lo, hi, sp);
    float s = lo + hi;
    s += __shfl_xor_sync(0xffffffffu, s, 1);   // full K=64 sum on both lanes
    x  = fmaf(dt, (s + ut) - x, x);            // x += dt*(-x + rec + u)
    th = tanh_fast(x);
}

__global__ __launch_bounds__(128, 1)
void rec_kernel(const float* __restrict__ u, const float* __restrict__ Wrec,
                const float* __restrict__ dtp, float* __restrict__ xmem) {
    const int b   = blockIdx.x;
    const int tid = threadIdx.x;
    const int c   = tid >> 1;
    const int h   = tid & 1;

    __shared__ __align__(16) float th_sh[2][CC];

    // W_rec row-half as 16 packed pairs (8B-aligned source)
    unsigned long long w2[16];
    const unsigned long long* wp =
        (const unsigned long long*)(Wrec + c * CC + h * 32);
#pragma unroll
    for (int j = 0; j < 16; j++) w2[j] = wp[j];

    const float dt = *dtp;
    const float4* ub4 = (const float4*)(u    + (b * CC + c) * TT);
    float4*       xb4 = (float4*)      (xmem + (b * CC + c) * TT);

    float x = 0.0f, th = 0.0f;   // x0 = 0, tanh(0) = 0
    float4 ucur  = ub4[0];
    float4 unext = ub4[1];

    for (int t0 = 0; t0 < TT; t0 += 4) {
        float4 xout;
        rec_step(x, th, ucur.x, 0, c, h, dt, w2, th_sh); xout.x = x;
        rec_step(x, th, ucur.y, 1, c, h, dt, w2, th_sh); xout.y = x;
        rec_step(x, th, ucur.z, 0, c, h, dt, w2, th_sh); xout.z = x;
        rec_step(x, th, ucur.w, 1, c, h, dt, w2, th_sh); xout.w = x;
        if (h == 0) xb4[t0 >> 2] = xout;           // membrane trace
        ucur = unext;
        if (t0 + 8 < TT) unext = ub4[(t0 >> 2) + 2];
    }
}

// ---------------------------------------------------------------------------
// Kernel 2: time-parallel readout  y[b,c,t] = sum_k Wff[c,k]*x[b,k,t] + bff[c]
// Block = (t-tile of 128, batch b); x tile staged in shared (warp-broadcast
// reads), W_ff staged transposed. Inner MAC uses packed FFMA2 (2 instr per
// LDS.128 instead of 4 FFMA).
// ---------------------------------------------------------------------------
__global__ __launch_bounds__(256)
void ff_kernel(const float* __restrict__ xmem, const float* __restrict__ Wff,
               const float* __restrict__ bff, float* __restrict__ y) {
    const int tt  = blockIdx.x;          // 0..31  -> t0 = tt*128
    const int b   = blockIdx.y;          // 0..63
    const int tid = threadIdx.x;         // 0..255
    const int c   = tid & 63;
    const int q   = tid >> 6;            // t-quarter 0..3
    const int t0  = tt * 128;

    __shared__ __align__(16) float xs[CC * 128];   // [k][t] row-major, 32 KB
    __shared__ float wsh[CC * CC];                  // transposed: wsh[k*64+c]

    // stage x tile (coalesced along t)
    const float4* xg4 = (const float4*)xmem;
    float4* xs4 = (float4*)xs;
#pragma unroll
    for (int i = 0; i < 8; i++) {
        int f   = tid + 256 * i;         // 0..2047 float4s
        int row = f >> 5;
        int col = f & 31;
        xs4[f] = xg4[(b * CC + row) * (TT / 4) + (t0 >> 2) + col];
    }
    // stage W_ff transposed
#pragma unroll
    for (int i = 0; i < 16; i++) {
        int f = tid + 256 * i;           // f = c_src*64 + k_src
        int csrc = f >> 6, ksrc = f & 63;
        wsh[ksrc * 64 + csrc] = Wff[f];
    }

    const float bias = bff[c];
    unsigned long long acc[16];          // 8 j-slots x 2 packed pairs
    unsigned long long bp = pk2(bias, bias);
#pragma unroll
    for (int j = 0; j < 16; j++) acc[j] = bp;

    __syncthreads();

    const ulonglong2* xrowq = (const ulonglong2*)(xs) + q * 8;
#pragma unroll 8
    for (int k = 0; k < CC; k++) {
        float wv = wsh[k * 64 + c];                 // conflict-free LDS
        unsigned long long wp = pk2(wv, wv);
        const ulonglong2* xr = xrowq + k * 32;
#pragma unroll
        for (int j = 0; j < 8; j++) {
            ulonglong2 v = xr[j];                   // warp-broadcast LDS.128
            acc[2 * j + 0] = fma2(wp, v.x, acc[2 * j + 0]);
            acc[2 * j + 1] = fma2(wp, v.y, acc[2 * j + 1]);
        }
    }

    ulonglong2* y4 = (ulonglong2*)(y + (b * CC + c) * TT + t0 + q * 32);
#pragma unroll
    for (int j = 0; j < 8; j++) {
        ulonglong2 o; o.x = acc[2 * j]; o.y = acc[2 * j + 1];
        y4[j] = o;
    }
}

// ---------------------------------------------------------------------------
extern "C" void kernel_launch(void* const* d_in, const int* in_sizes, int n_in,
                              void* d_out, int out_size) {
    const float* u    = (const float*)d_in[0];   // [B,C,T]
    const float* Wrec = (const float*)d_in[1];   // [C,C]
    const float* Wff  = (const float*)d_in[2];   // [C,C]
    const float* bff  = (const float*)d_in[3];   // [C]
    const float* dtp  = (const float*)d_in[4];   // scalar

    float* out  = (float*)d_out;
    float* yout = out;                            // outputs [B,C,T]
    float* xmem = out + (size_t)BB * CC * TT;     // membrane_potentials [B,C,T]

    rec_kernel<<<BB, 128>>>(u, Wrec, dtp, xmem);

    dim3 g2(TT / 128, BB);
    ff_kernel<<<g2, 256>>>(xmem, Wff, bff, yout);
}

// round 7
// speedup vs baseline: 1.3312x; 1.2392x over previous
#include <cuda_runtime.h>

#define BB 64
#define CC 64
#define TT 4096

// ---- packed f32x2 helpers (Blackwell FFMA2 path, PTX-only) -----------------
__device__ __forceinline__ unsigned long long pk2(float lo, float hi) {
    unsigned long long r;
    asm("mov.b64 %0, {%1, %2};" : "=l"(r) : "f"(lo), "f"(hi));
    return r;
}
__device__ __forceinline__ void upk2(float& lo, float& hi, unsigned long long v) {
    asm("mov.b64 {%0, %1}, %2;" : "=f"(lo), "=f"(hi) : "l"(v));
}
__device__ __forceinline__ unsigned long long fma2(unsigned long long a,
                                                   unsigned long long b,
                                                   unsigned long long c) {
    unsigned long long d;
    asm("fma.rn.f32x2 %0, %1, %2, %3;" : "=l"(d) : "l"(a), "l"(b), "l"(c));
    return d;
}
__device__ __forceinline__ unsigned long long add2(unsigned long long a,
                                                   unsigned long long b) {
    unsigned long long d;
    asm("add.rn.f32x2 %0, %1, %2;" : "=l"(d) : "l"(a), "l"(b));
    return d;
}
__device__ __forceinline__ unsigned long long mul2(unsigned long long a,
                                                   unsigned long long b) {
    unsigned long long d;
    asm("mul.rn.f32x2 %0, %1, %2;" : "=l"(d) : "l"(a), "l"(b));
    return d;
}

// HW tanh: single MUFU.TANH, ~16 cyc, abs err ~6e-4 (error-transfer into the
// output measured at ~0.5x -> expected output rel_err ~2-4e-4 < 1e-3 gate).
__device__ __forceinline__ float tanh_hw(float x) {
    float r;
    asm("tanh.approx.f32 %0, %1;" : "=f"(r) : "f"(x));
    return r;
}

// ---------------------------------------------------------------------------
// Kernel 1: sequential recurrence, one CTA per batch row.
// 128 threads: thread = (channel c = tid>>1, K-half h = tid&1).
// Weights pre-scaled by dt and held as 16 packed f32x2 registers.
// tanh broadcast via double-buffered shared array, ONE __syncthreads/step.
// Lane pair (2c,2c+1) reduces halves with shfl_xor; both lanes update x
// bit-identically. Update: x = part + base, base precomputed off-path.
// ---------------------------------------------------------------------------
__device__ __forceinline__ void rec_step(
    float& x, float& th, float ut, int buf, int c, int h,
    float dt, float omd,
    const unsigned long long* __restrict__ w2, float (*th_sh)[CC])
{
    // off-critical-path: base = (1-dt)*x + dt*u
    float base = fmaf(dt, ut, omd * x);
    if (h == 0) th_sh[buf][c] = th;
    __syncthreads();
    const ulonglong2* thv = (const ulonglong2*)(&th_sh[buf][h * 32]);
    unsigned long long a0 = 0ull, a1 = 0ull, a2 = 0ull, a3 = 0ull;
#pragma unroll
    for (int j = 0; j < 8; j += 2) {
        ulonglong2 v0 = thv[j];
        ulonglong2 v1 = thv[j + 1];
        a0 = fma2(w2[2 * j + 0], v0.x, a0);
        a1 = fma2(w2[2 * j + 1], v0.y, a1);
        a2 = fma2(w2[2 * j + 2], v1.x, a2);
        a3 = fma2(w2[2 * j + 3], v1.y, a3);
    }
    unsigned long long sp = add2(add2(a0, a1), add2(a2, a3));
    float lo, hi; upk2(lo, hi, sp);
    float part = lo + hi;                           // this half's dt*W*th
    part += __shfl_xor_sync(0xffffffffu, part, 1);  // full K=64, both lanes
    x  = part + base;                               // 1 FADD post-shfl
    th = tanh_hw(x);
}

__global__ __launch_bounds__(128, 1)
void rec_kernel(const float* __restrict__ u, const float* __restrict__ Wrec,
                const float* __restrict__ dtp, float* __restrict__ xmem) {
    const int b   = blockIdx.x;
    const int tid = threadIdx.x;
    const int c   = tid >> 1;
    const int h   = tid & 1;

    __shared__ __align__(16) float th_sh[2][CC];

    const float dt  = *dtp;
    const float omd = 1.0f - dt;
    const unsigned long long dt2 = pk2(dt, dt);

    // W_rec row-half, pre-scaled by dt, as 16 packed pairs
    unsigned long long w2[16];
    const unsigned long long* wp =
        (const unsigned long long*)(Wrec + c * CC + h * 32);
#pragma unroll
    for (int j = 0; j < 16; j++) w2[j] = mul2(wp[j], dt2);

    const float4* ub4 = (const float4*)(u    + (b * CC + c) * TT);
    float4*       xb4 = (float4*)      (xmem + (b * CC + c) * TT);

    float x = 0.0f, th = 0.0f;   // x0 = 0, tanh(0) = 0
    float4 ucur  = ub4[0];
    float4 unext = ub4[1];

    for (int t0 = 0; t0 < TT; t0 += 4) {
        float4 xout;
        rec_step(x, th, ucur.x, 0, c, h, dt, omd, w2, th_sh); xout.x = x;
        rec_step(x, th, ucur.y, 1, c, h, dt, omd, w2, th_sh); xout.y = x;
        rec_step(x, th, ucur.z, 0, c, h, dt, omd, w2, th_sh); xout.z = x;
        rec_step(x, th, ucur.w, 1, c, h, dt, omd, w2, th_sh); xout.w = x;
        if (h == 0) xb4[t0 >> 2] = xout;           // membrane trace
        ucur = unext;
        if (t0 + 8 < TT) unext = ub4[(t0 >> 2) + 2];
    }
}

// ---------------------------------------------------------------------------
// Kernel 2: time-parallel readout  y[b,c,t] = sum_k Wff[c,k]*x[b,k,t] + bff[c]
// R4 showed L1=92% / fma=25% -> LDS-bound. Register-block 4 channels x 8 t
// per thread: per k only 3 LDS.128 (2 for x-oct, 1 for w-quad) feed 16 FFMA2
// -> 3x less shared traffic per MAC.
// ---------------------------------------------------------------------------
__global__ __launch_bounds__(256)
void ff_kernel(const float* __restrict__ xmem, const float* __restrict__ Wff,
               const float* __restrict__ bff, float* __restrict__ y) {
    const int tt  = blockIdx.x;          // 0..31  -> t0 = tt*128
    const int b   = blockIdx.y;          // 0..63
    const int tid = threadIdx.x;         // 0..255
    const int tq  = tid & 15;            // t-oct index: t = t0 + tq*8 .. +7
    const int cq  = tid >> 4;            // c-quad index: c = cq*4 .. +3
    const int t0  = tt * 128;

    __shared__ __align__(16) float xs[CC * 128];   // [k][t], 32 KB
    __shared__ __align__(16) float wsh[CC * CC];   // transposed: wsh[k*64+c]

    // stage x tile (coalesced along t)
    const float4* xg4 = (const float4*)xmem;
    float4* xs4 = (float4*)xs;
#pragma unroll
    for (int i = 0; i < 8; i++) {
        int f   = tid + 256 * i;         // 0..2047 float4s
        int row = f >> 5;
        int col = f & 31;
        xs4[f] = xg4[(b * CC + row) * (TT / 4) + (t0 >> 2) + col];
    }
    // stage W_ff transposed
#pragma unroll
    for (int i = 0; i < 16; i++) {
        int f = tid + 256 * i;           // f = c_src*64 + k_src
        int csrc = f >> 6, ksrc = f & 63;
        wsh[ksrc * 64 + csrc] = Wff[f];
    }

    // accumulators: 4 channels x 4 t-pairs (packed) = 16 u64
    const float4 bv = *(const float4*)(bff + cq * 4);
    unsigned long long acc[4][4];
#pragma unroll
    for (int p = 0; p < 4; p++) {
        acc[0][p] = pk2(bv.x, bv.x);
        acc[1][p] = pk2(bv.y, bv.y);
        acc[2][p] = pk2(bv.z, bv.z);
        acc[3][p] = pk2(bv.w, bv.w);
    }

    __syncthreads();

#pragma unroll 4
    for (int k = 0; k < CC; k++) {
        const ulonglong2* xr = (const ulonglong2*)(xs + k * 128 + tq * 8);
        ulonglong2 xv0 = xr[0];          // t-pairs 0,1
        ulonglong2 xv1 = xr[1];          // t-pairs 2,3
        const float4 wq = *(const float4*)(wsh + k * 64 + cq * 4);
        unsigned long long w0 = pk2(wq.x, wq.x);
        unsigned long long w1 = pk2(wq.y, wq.y);
        unsigned long long w2 = pk2(wq.z, wq.z);
        unsigned long long w3 = pk2(wq.w, wq.w);
        acc[0][0] = fma2(w0, xv0.x, acc[0][0]);
        acc[0][1] = fma2(w0, xv0.y, acc[0][1]);
        acc[0][2] = fma2(w0, xv1.x, acc[0][2]);
        acc[0][3] = fma2(w0, xv1.y, acc[0][3]);
        acc[1][0] = fma2(w1, xv0.x, acc[1][0]);
        acc[1][1] = fma2(w1, xv0.y, acc[1][1]);
        acc[1][2] = fma2(w1, xv1.x, acc[1][2]);
        acc[1][3] = fma2(w1, xv1.y, acc[1][3]);
        acc[2][0] = fma2(w2, xv0.x, acc[2][0]);
        acc[2][1] = fma2(w2, xv0.y, acc[2][1]);
        acc[2][2] = fma2(w2, xv1.x, acc[2][2]);
        acc[2][3] = fma2(w2, xv1.y, acc[2][3]);
        acc[3][0] = fma2(w3, xv0.x, acc[3][0]);
        acc[3][1] = fma2(w3, xv0.y, acc[3][1]);
        acc[3][2] = fma2(w3, xv1.x, acc[3][2]);
        acc[3][3] = fma2(w3, xv1.y, acc[3][3]);
    }

    // store: 4 channels x 8 t (32B each, coalesced across tq)
#pragma unroll
    for (int ci = 0; ci < 4; ci++) {
        ulonglong2* y4 =
            (ulonglong2*)(y + (size_t)(b * CC + cq * 4 + ci) * TT + t0 + tq * 8);
        ulonglong2 o0; o0.x = acc[ci][0]; o0.y = acc[ci][1];
        ulonglong2 o1; o1.x = acc[ci][2]; o1.y = acc[ci][3];
        y4[0] = o0;
        y4[1] = o1;
    }
}

// ---------------------------------------------------------------------------
extern "C" void kernel_launch(void* const* d_in, const int* in_sizes, int n_in,
                              void* d_out, int out_size) {
    const float* u    = (const float*)d_in[0];   // [B,C,T]
    const float* Wrec = (const float*)d_in[1];   // [C,C]
    const float* Wff  = (const float*)d_in[2];   // [C,C]
    const float* bff  = (const float*)d_in[3];   // [C]
    const float* dtp  = (const float*)d_in[4];   // scalar

    float* out  = (float*)d_out;
    float* yout = out;                            // outputs [B,C,T]
    float* xmem = out + (size_t)BB * CC * TT;     // membrane_potentials [B,C,T]

    rec_kernel<<<BB, 128>>>(u, Wrec, dtp, xmem);

    dim3 g2(TT / 128, BB);
    ff_kernel<<<g2, 256>>>(xmem, Wff, bff, yout);
}

// round 9
// speedup vs baseline: 1.6140x; 1.2125x over previous
#include <cuda_runtime.h>

#define BB 64
#define CC 64
#define TT 4096

// ---- packed f32x2 helpers (Blackwell FFMA2 path, PTX-only) -----------------
__device__ __forceinline__ unsigned long long pk2(float lo, float hi) {
    unsigned long long r;
    asm("mov.b64 %0, {%1, %2};" : "=l"(r) : "f"(lo), "f"(hi));
    return r;
}
__device__ __forceinline__ void upk2(float& lo, float& hi, unsigned long long v) {
    asm("mov.b64 {%0, %1}, %2;" : "=f"(lo), "=f"(hi) : "l"(v));
}
__device__ __forceinline__ unsigned long long fma2(unsigned long long a,
                                                   unsigned long long b,
                                                   unsigned long long c) {
    unsigned long long d;
    asm("fma.rn.f32x2 %0, %1, %2, %3;" : "=l"(d) : "l"(a), "l"(b), "l"(c));
    return d;
}
__device__ __forceinline__ unsigned long long add2(unsigned long long a,
                                                   unsigned long long b) {
    unsigned long long d;
    asm("add.rn.f32x2 %0, %1, %2;" : "=l"(d) : "l"(a), "l"(b));
    return d;
}
__device__ __forceinline__ unsigned long long mul2(unsigned long long a,
                                                   unsigned long long b) {
    unsigned long long d;
    asm("mul.rn.f32x2 %0, %1, %2;" : "=l"(d) : "l"(a), "l"(b));
    return d;
}

// HW tanh (MUFU.TANH): measured output rel_err 1.6e-5 on this problem.
__device__ __forceinline__ float tanh_hw(float x) {
    float r;
    asm("tanh.approx.f32 %0, %1;" : "=f"(r) : "f"(x));
    return r;
}

// ---------------------------------------------------------------------------
// Kernel 1: sequential recurrence, one CTA per batch row.
// 64 threads (2 warps): thread = channel c, FULL K=64 dot per thread.
//  - no shfl on the critical path
//  - barrier is nw=2 (cheap)
//  - th broadcast: 1 STS.32 (coalesced) + 16 LDS.128 all-lane-broadcast (1 wf)
//  - W_rec row (pre-scaled by dt) lives in 32 packed f32x2 registers
//  - x update: x = s + base, base=(1-dt)x+dt*u precomputed before the barrier
// ---------------------------------------------------------------------------
__device__ __forceinline__ void rec_step(
    float& x, float& th, float ut, int buf, int c,
    float dt, float omd,
    const unsigned long long* __restrict__ w2, float (*th_sh)[CC])
{
    // off-critical-path: base = (1-dt)*x + dt*u
    float base = fmaf(dt, ut, omd * x);
    th_sh[buf][c] = th;                 // coalesced STS.32
    __syncthreads();                    // 2-warp barrier
    const ulonglong2* thv = (const ulonglong2*)(th_sh[buf]);
    unsigned long long a0 = 0ull, a1 = 0ull, a2 = 0ull, a3 = 0ull;
#pragma unroll
    for (int j = 0; j < 8; j++) {       // 16 LDS.128 (broadcast), 32 FFMA2
        ulonglong2 v0 = thv[2 * j];
        ulonglong2 v1 = thv[2 * j + 1];
        a0 = fma2(w2[4 * j + 0], v0.x, a0);
        a1 = fma2(w2[4 * j + 1], v0.y, a1);
        a2 = fma2(w2[4 * j + 2], v1.x, a2);
        a3 = fma2(w2[4 * j + 3], v1.y, a3);
    }
    unsigned long long sp = add2(add2(a0, a1), add2(a2, a3));
    float lo, hi; upk2(lo, hi, sp);
    float s = lo + hi;                  // full K=64 dot (pre-scaled by dt)
    x  = s + base;
    th = tanh_hw(x);
}

__global__ __launch_bounds__(64, 1)
void rec_kernel(const float* __restrict__ u, const float* __restrict__ Wrec,
                const float* __restrict__ dtp, float* __restrict__ xmem) {
    const int b = blockIdx.x;
    const int c = threadIdx.x;          // 0..63, one channel per thread

    __shared__ __align__(16) float th_sh[2][CC];

    const float dt  = *dtp;
    const float omd = 1.0f - dt;
    const unsigned long long dt2 = pk2(dt, dt);

    // full W_rec row, pre-scaled by dt, as 32 packed k-pairs
    unsigned long long w2[32];
    const unsigned long long* wp = (const unsigned long long*)(Wrec + c * CC);
#pragma unroll
    for (int j = 0; j < 32; j++) w2[j] = mul2(wp[j], dt2);

    const float4* ub4 = (const float4*)(u    + (b * CC + c) * TT);
    float4*       xb4 = (float4*)      (xmem + (b * CC + c) * TT);

    float x = 0.0f, th = 0.0f;          // x0 = 0, tanh(0) = 0
    float4 ucur  = ub4[0];
    float4 unext = ub4[1];

    for (int t0 = 0; t0 < TT; t0 += 4) {
        float4 xout;
        rec_step(x, th, ucur.x, 0, c, dt, omd, w2, th_sh); xout.x = x;
        rec_step(x, th, ucur.y, 1, c, dt, omd, w2, th_sh); xout.y = x;
        rec_step(x, th, ucur.z, 0, c, dt, omd, w2, th_sh); xout.z = x;
        rec_step(x, th, ucur.w, 1, c, dt, omd, w2, th_sh); xout.w = x;
        xb4[t0 >> 2] = xout;            // membrane trace (every thread owns a row)
        ucur = unext;
        if (t0 + 8 < TT) unext = ub4[(t0 >> 2) + 2];
    }
}

// ---------------------------------------------------------------------------
// Kernel 2: time-parallel readout  y[b,c,t] = sum_k Wff[c,k]*x[b,k,t] + bff[c]
// 4 channels x 8 t register blocking. wsh holds W transposed with an XOR
// float4-swizzle: W[c,k] at  k*64 + ((c>>2 ^ (k&15))<<2 | (c&3)).
// This turns the 32-way staging STS conflict (lane stride 64 floats) into
// a 4-way one while keeping mainloop weight loads a single float4 LDS.
// ---------------------------------------------------------------------------
__global__ __launch_bounds__(256)
void ff_kernel(const float* __restrict__ xmem, const float* __restrict__ Wff,
               const float* __restrict__ bff, float* __restrict__ y) {
    const int tt  = blockIdx.x;          // 0..31  -> t0 = tt*128
    const int b   = blockIdx.y;          // 0..63
    const int tid = threadIdx.x;         // 0..255
    const int tq  = tid & 15;            // t-oct index: t = t0 + tq*8 .. +7
    const int cq  = tid >> 4;            // c-quad index: c = cq*4 .. +3
    const int t0  = tt * 128;

    __shared__ __align__(16) float xs[CC * 128];   // [k][t], 32 KB
    __shared__ __align__(16) float wsh[CC * CC];   // swizzled transposed W

    // stage x tile (coalesced along t)
    const float4* xg4 = (const float4*)xmem;
    float4* xs4 = (float4*)xs;
#pragma unroll
    for (int i = 0; i < 8; i++) {
        int f   = tid + 256 * i;         // 0..2047 float4s
        int row = f >> 5;
        int col = f & 31;
        xs4[f] = xg4[(b * CC + row) * (TT / 4) + (t0 >> 2) + col];
    }
    // stage W_ff transposed + swizzled
#pragma unroll
    for (int i = 0; i < 16; i++) {
        int f = tid + 256 * i;           // f = c_src*64 + k_src
        int csrc = f >> 6, ksrc = f & 63;
        int idx = ksrc * 64 + ((((csrc >> 2) ^ (ksrc & 15)) << 2) | (csrc & 3));
        wsh[idx] = Wff[f];
    }

    // accumulators: 4 channels x 4 t-pairs (packed) = 16 u64
    const float4 bv = *(const float4*)(bff + cq * 4);
    unsigned long long acc[4][4];
#pragma unroll
    for (int p = 0; p < 4; p++) {
        acc[0][p] = pk2(bv.x, bv.x);
        acc[1][p] = pk2(bv.y, bv.y);
        acc[2][p] = pk2(bv.z, bv.z);
        acc[3][p] = pk2(bv.w, bv.w);
    }

    __syncthreads();

#pragma unroll 4
    for (int k = 0; k < CC; k++) {
        const ulonglong2* xr = (const ulonglong2*)(xs + k * 128 + tq * 8);
        ulonglong2 xv0 = xr[0];          // t-pairs 0,1
        ulonglong2 xv1 = xr[1];          // t-pairs 2,3
        const float4 wq =
            *(const float4*)(wsh + k * 64 + ((cq ^ (k & 15)) << 2));
        unsigned long long w0 = pk2(wq.x, wq.x);
        unsigned long long w1 = pk2(wq.y, wq.y);
        unsigned long long w2 = pk2(wq.z, wq.z);
        unsigned long long w3 = pk2(wq.w, wq.w);
        acc[0][0] = fma2(w0, xv0.x, acc[0][0]);
        acc[0][1] = fma2(w0, xv0.y, acc[0][1]);
        acc[0][2] = fma2(w0, xv1.x, acc[0][2]);
        acc[0][3] = fma2(w0, xv1.y, acc[0][3]);
        acc[1][0] = fma2(w1, xv0.x, acc[1][0]);
        acc[1][1] = fma2(w1, xv0.y, acc[1][1]);
        acc[1][2] = fma2(w1, xv1.x, acc[1][2]);
        acc[1][3] = fma2(w1, xv1.y, acc[1][3]);
        acc[2][0] = fma2(w2, xv0.x, acc[2][0]);
        acc[2][1] = fma2(w2, xv0.y, acc[2][1]);
        acc[2][2] = fma2(w2, xv1.x, acc[2][2]);
        acc[2][3] = fma2(w2, xv1.y, acc[2][3]);
        acc[3][0] = fma2(w3, xv0.x, acc[3][0]);
        acc[3][1] = fma2(w3, xv0.y, acc[3][1]);
        acc[3][2] = fma2(w3, xv1.x, acc[3][2]);
        acc[3][3] = fma2(w3, xv1.y, acc[3][3]);
    }

    // store: 4 channels x 8 t (32B each, coalesced across tq)
#pragma unroll
    for (int ci = 0; ci < 4; ci++) {
        ulonglong2* y4 =
            (ulonglong2*)(y + (size_t)(b * CC + cq * 4 + ci) * TT + t0 + tq * 8);
        ulonglong2 o0; o0.x = acc[ci][0]; o0.y = acc[ci][1];
        ulonglong2 o1; o1.x = acc[ci][2]; o1.y = acc[ci][3];
        y4[0] = o0;
        y4[1] = o1;
    }
}

// ---------------------------------------------------------------------------
extern "C" void kernel_launch(void* const* d_in, const int* in_sizes, int n_in,
                              void* d_out, int out_size) {
    const float* u    = (const float*)d_in[0];   // [B,C,T]
    const float* Wrec = (const float*)d_in[1];   // [C,C]
    const float* Wff  = (const float*)d_in[2];   // [C,C]
    const float* bff  = (const float*)d_in[3];   // [C]
    const float* dtp  = (const float*)d_in[4];   // scalar

    float* out  = (float*)d_out;
    float* yout = out;                            // outputs [B,C,T]
    float* xmem = out + (size_t)BB * CC * TT;     // membrane_potentials [B,C,T]

    rec_kernel<<<BB, 64>>>(u, Wrec, dtp, xmem);

    dim3 g2(TT / 128, BB);
    ff_kernel<<<g2, 256>>>(xmem, Wff, bff, yout);
}